// round 8
// baseline (speedup 1.0000x reference)
#include <cuda_runtime.h>
#include <math.h>
#include <stdint.h>

#define DIMC 256
#define HEADS 8
#define NTOK 64
#define BATCH 32
#define LTOK 4096
#define M_ROWS (BATCH*LTOK)  // 131072
#define SHIFT_ 4

// ---------------- scratch ----------------
static __device__ float g_xw[(size_t)M_ROWS * DIMC];          // tf32-rounded windowed x
static __device__ float g_qkv[(size_t)M_ROWS * 3 * DIMC];
static __device__ float g_attnout[(size_t)M_ROWS * DIMC];     // tf32-rounded
static __device__ float g_tmp[(size_t)M_ROWS * DIMC];
static __device__ float g_xr[(size_t)M_ROWS * DIMC];          // full fp32 (residual)
static __device__ float g_xrt[(size_t)M_ROWS * DIMC];         // tf32-rounded (fc1 A)
static __device__ float g_hdn[(size_t)M_ROWS * 4 * DIMC];     // tf32-rounded
static __device__ float g_wt[786432];                         // rounded weights
static __device__ float g_cpb[225 * HEADS];
static __device__ float g_bias16[HEADS * NTOK * NTOK];
static __device__ float g_qkvb[3 * DIMC];

#define WT_QKV 0
#define WT_PROJ 196608
#define WT_FC1 262144
#define WT_FC2 524288

__device__ __forceinline__ uint32_t tf32u(float x) {
    uint32_t o;
    asm("cvt.rna.tf32.f32 %0, %1;" : "=r"(o) : "f"(x));
    return o;
}
__device__ __forceinline__ float tf32r(float x) { return __uint_as_float(tf32u(x)); }

// ---------------- tiny setup kernels ----------------
__global__ void fill_qkvb_kernel(const float* __restrict__ q_bias,
                                 const float* __restrict__ v_bias) {
    int t = threadIdx.x;
    float v;
    if (t < 256)      v = q_bias[t];
    else if (t < 512) v = 0.f;
    else              v = v_bias[t - 512];
    g_qkvb[t] = v;
}

__global__ void cpb_kernel(const float* __restrict__ w1, const float* __restrict__ b1,
                           const float* __restrict__ w2) {
    int i = threadIdx.x;
    if (i >= 225) return;
    float a  = (float)(i / 15) - 7.f;
    float bb = (float)(i % 15) - 7.f;
    float f0 = a  * (8.f / 7.f);
    float f1 = bb * (8.f / 7.f);
    f0 = copysignf(log2f(fabsf(f0) + 1.f) * (1.f / 3.f), f0);
    f1 = copysignf(log2f(fabsf(f1) + 1.f) * (1.f / 3.f), f1);
    float acc[HEADS];
#pragma unroll
    for (int h = 0; h < HEADS; h++) acc[h] = 0.f;
    for (int u = 0; u < 512; u++) {
        float hu = fmaf(w1[2 * u], f0, fmaf(w1[2 * u + 1], f1, b1[u]));
        hu = fmaxf(hu, 0.f);
#pragma unroll
        for (int h = 0; h < HEADS; h++) acc[h] = fmaf(hu, w2[h * 512 + u], acc[h]);
    }
#pragma unroll
    for (int h = 0; h < HEADS; h++) g_cpb[i * HEADS + h] = acc[h];
}

__global__ void bias16_kernel() {
    int gid = blockIdx.x * blockDim.x + threadIdx.x;
    if (gid >= HEADS * NTOK * NTOK) return;
    int h = gid >> 12;
    int ij = gid & 4095;
    int i = ij >> 6, j = ij & 63;
    int dr = (i >> 3) - (j >> 3);
    int dc = (i & 7) - (j & 7);
    int idx = (dr + 7) * 15 + (dc + 7);
    float x = g_cpb[idx * HEADS + h];
    g_bias16[gid] = 16.f / (1.f + expf(-x));
}

__global__ void round_w_kernel(const float* __restrict__ qkv_w, const float* __restrict__ proj_w,
                               const float* __restrict__ fc1_w, const float* __restrict__ fc2_w) {
    int i4 = blockIdx.x * blockDim.x + threadIdx.x;
    if (i4 >= 196608) return;
    const float* src;
    int off = i4 * 4;
    if (off < WT_PROJ)           { src = qkv_w  + off; }
    else if (off < WT_FC1)       { src = proj_w + (off - WT_PROJ); }
    else if (off < WT_FC2)       { src = fc1_w  + (off - WT_FC1); }
    else                         { src = fc2_w  + (off - WT_FC2); }
    float4 v = *(const float4*)src;
    v.x = tf32r(v.x); v.y = tf32r(v.y); v.z = tf32r(v.z); v.w = tf32r(v.w);
    *(float4*)(g_wt + off) = v;
}

__global__ void gather_round_kernel(const float* __restrict__ x) {
    int t = blockIdx.x * blockDim.x + threadIdx.x;
    int m = t >> 6, c4 = t & 63;
    int win = m >> 6, n = m & 63;
    int b = win >> 6, wr = (win >> 3) & 7, wc = win & 7;
    int r = (wr * 8 + (n >> 3) + SHIFT_) & 63;
    int c = (wc * 8 + (n & 7) + SHIFT_) & 63;
    float4 v = ((const float4*)(x + ((size_t)b * LTOK + r * 64 + c) * DIMC))[c4];
    v.x = tf32r(v.x); v.y = tf32r(v.y); v.z = tf32r(v.z); v.w = tf32r(v.w);
    ((float4*)(g_xw + (size_t)m * DIMC))[c4] = v;
}

// ---------------- tf32 mma.sync GEMM, 256x128 CTA tile, 8 warps of 64x64 ----------------
// C[M,N] = A[M,K] @ W[N,K]^T + bias.  BK=16, 3-stage cp.async.
#define TBK 16
#define ROWF 20                  // padded row (floats)
#define AROWB (ROWF * 4)         // 80 bytes
#define A_STAGEB (256 * AROWB)   // 20480
#define B_STAGEB (128 * AROWB)   // 10240
#define SLOTB (A_STAGEB + B_STAGEB)  // 30720
#define GSTAGES 3

#define CP16(sm_, gp_) asm volatile("cp.async.cg.shared.global [%0], [%1], 16;" :: "r"(sm_), "l"(gp_))
#define CPCOMMIT() asm volatile("cp.async.commit_group;" ::: "memory")

__global__ __launch_bounds__(256, 1) void mma_gemm_kernel(
    const float* __restrict__ A, const float* __restrict__ W,
    const float* __restrict__ bias, float* __restrict__ C,
    int N, int K, int gelu) {
    extern __shared__ float sm[];
    int tid = threadIdx.x;
    int wid = tid >> 5, lane = tid & 31;
    int wr = wid >> 1, wc = wid & 1;       // warp tile origin (wr*64, wc*64)
    int brow = blockIdx.y * 256, bcol = blockIdx.x * 128;
    int lq = lane >> 2, lr = lane & 3;

    // cp.async assignments: A 1024 chunks (4/thread), B 512 chunks (2/thread)
    int arow = tid >> 2, ac4 = (tid & 3) * 4;     // A: rows tid>>2 + i*64
    const float* aptr = A + (size_t)(brow + arow) * K + ac4;
    int brow_l = tid >> 2, bc4 = (tid & 3) * 4;
    const float* wptr = W + (size_t)(bcol + brow_l) * K + bc4;

    uint32_t sbase = (uint32_t)__cvta_generic_to_shared(sm);
    uint32_t aoff = sbase + arow * AROWB + ac4 * 4;
    uint32_t woff = sbase + A_STAGEB + brow_l * AROWB + bc4 * 4;
    const uint32_t arow64 = 64 * AROWB;

    float acc[4][8][4];
#pragma unroll
    for (int mi = 0; mi < 4; mi++)
#pragma unroll
        for (int ni = 0; ni < 8; ni++)
#pragma unroll
            for (int r = 0; r < 4; r++) acc[mi][ni][r] = 0.f;

    int KT = K / TBK;
    // prologue: prefetch tiles 0,1
#pragma unroll
    for (int p = 0; p < 2; p++) {
        uint32_t bo = p * (uint32_t)SLOTB;
        int k0 = p * TBK;
#pragma unroll
        for (int i = 0; i < 4; i++) CP16(aoff + bo + i * arow64, aptr + (size_t)i * 64 * K + k0);
#pragma unroll
        for (int i = 0; i < 2; i++) CP16(woff + bo + i * arow64, wptr + (size_t)i * 64 * K + k0);
        CPCOMMIT();
    }

    for (int kt = 0; kt < KT; kt++) {
        if (kt == KT - 1) asm volatile("cp.async.wait_group 0;" ::: "memory");
        else              asm volatile("cp.async.wait_group 1;" ::: "memory");
        __syncthreads();
        if (kt + 2 < KT) {
            uint32_t bo = ((kt + 2) % GSTAGES) * (uint32_t)SLOTB;
            int k0 = (kt + 2) * TBK;
#pragma unroll
            for (int i = 0; i < 4; i++) CP16(aoff + bo + i * arow64, aptr + (size_t)i * 64 * K + k0);
#pragma unroll
            for (int i = 0; i < 2; i++) CP16(woff + bo + i * arow64, wptr + (size_t)i * 64 * K + k0);
        }
        CPCOMMIT();   // empty group when nothing prefetched keeps wait_group 1 sound

        const float* sa = sm + (kt % GSTAGES) * (SLOTB / 4);
        const float* sw = sa + (A_STAGEB / 4);
#pragma unroll
        for (int kk = 0; kk < TBK; kk += 8) {
            uint32_t af[4][4];
#pragma unroll
            for (int mi = 0; mi < 4; mi++) {
                int rb = wr * 64 + mi * 16 + lq;
                af[mi][0] = __float_as_uint(sa[rb * ROWF + kk + lr]);
                af[mi][1] = __float_as_uint(sa[(rb + 8) * ROWF + kk + lr]);
                af[mi][2] = __float_as_uint(sa[rb * ROWF + kk + 4 + lr]);
                af[mi][3] = __float_as_uint(sa[(rb + 8) * ROWF + kk + 4 + lr]);
            }
            uint32_t bf[8][2];
#pragma unroll
            for (int ni = 0; ni < 8; ni++) {
                int nb = wc * 64 + ni * 8 + lq;
                bf[ni][0] = __float_as_uint(sw[nb * ROWF + kk + lr]);
                bf[ni][1] = __float_as_uint(sw[nb * ROWF + kk + 4 + lr]);
            }
#pragma unroll
            for (int mi = 0; mi < 4; mi++)
#pragma unroll
                for (int ni = 0; ni < 8; ni++) {
                    asm volatile(
                        "mma.sync.aligned.m16n8k8.row.col.f32.tf32.tf32.f32 "
                        "{%0,%1,%2,%3}, {%4,%5,%6,%7}, {%8,%9}, {%0,%1,%2,%3};"
                        : "+f"(acc[mi][ni][0]), "+f"(acc[mi][ni][1]),
                          "+f"(acc[mi][ni][2]), "+f"(acc[mi][ni][3])
                        : "r"(af[mi][0]), "r"(af[mi][1]), "r"(af[mi][2]), "r"(af[mi][3]),
                          "r"(bf[ni][0]), "r"(bf[ni][1]));
                }
        }
    }

    // epilogue: bias (+ optional exact GELU + tf32 round), float2 writes
#pragma unroll
    for (int mi = 0; mi < 4; mi++) {
#pragma unroll
        for (int ni = 0; ni < 8; ni++) {
            int col = bcol + wc * 64 + ni * 8 + lr * 2;
            float b0 = bias[col], b1 = bias[col + 1];
            int rr = brow + wr * 64 + mi * 16 + lq;
            float v0 = acc[mi][ni][0] + b0;
            float v1 = acc[mi][ni][1] + b1;
            float v2 = acc[mi][ni][2] + b0;
            float v3 = acc[mi][ni][3] + b1;
            if (gelu) {
                v0 = tf32r(0.5f * v0 * (1.f + erff(v0 * 0.70710678118654752f)));
                v1 = tf32r(0.5f * v1 * (1.f + erff(v1 * 0.70710678118654752f)));
                v2 = tf32r(0.5f * v2 * (1.f + erff(v2 * 0.70710678118654752f)));
                v3 = tf32r(0.5f * v3 * (1.f + erff(v3 * 0.70710678118654752f)));
            }
            *(float2*)(C + (size_t)rr * N + col) = make_float2(v0, v1);
            *(float2*)(C + (size_t)(rr + 8) * N + col) = make_float2(v2, v3);
        }
    }
}

// ---------------- fused window attention, register-blocked ----------------
__global__ __launch_bounds__(256) void attn_kernel(const float* __restrict__ logit_scale) {
    __shared__ float qs[64][36];
    __shared__ float ksT[32][68];
    __shared__ float vs[64][36];
    __shared__ float Ss[64][68];
    __shared__ int lab[64];

    int blk = blockIdx.x;
    int win = blk >> 3, h = blk & 7;
    int t = threadIdx.x;

    size_t base = (size_t)win * 64 * 768;
#pragma unroll
    for (int f = t; f < 512; f += 256) {
        int n = f >> 3, d4 = (f & 7) * 4;
        const float* rowp = g_qkv + base + (size_t)n * 768 + h * 32 + d4;
        float4 q4 = *(const float4*)(rowp);
        float4 k4 = *(const float4*)(rowp + 256);
        float4 v4 = *(const float4*)(rowp + 512);
        *(float4*)&qs[n][d4] = q4;
        ksT[d4 + 0][n] = k4.x; ksT[d4 + 1][n] = k4.y;
        ksT[d4 + 2][n] = k4.z; ksT[d4 + 3][n] = k4.w;
        *(float4*)&vs[n][d4] = v4;
    }
    if (t < 64) {
        int wr = (win >> 3) & 7, wc = win & 7;
        int rs = wr * 8 + (t >> 3), cs = wc * 8 + (t & 7);
        int lr2 = rs < 56 ? 0 : (rs < 60 ? 1 : 2);
        int lc2 = cs < 56 ? 0 : (cs < 60 ? 1 : 2);
        lab[t] = lr2 * 3 + lc2;
    }
    __syncthreads();

    {
        int row = t >> 2, j0 = (t & 3) * 8;
        float sq = 0.f;
#pragma unroll
        for (int j = 0; j < 8; j++) { float a = qs[row][j0 + j]; sq = fmaf(a, a, sq); }
        sq += __shfl_xor_sync(0xffffffffu, sq, 1);
        sq += __shfl_xor_sync(0xffffffffu, sq, 2);
        float iq = 1.f / fmaxf(sqrtf(sq), 1e-12f);
#pragma unroll
        for (int j = 0; j < 8; j++) qs[row][j0 + j] *= iq;
    }
    {
        int tok = t >> 2, d0 = (t & 3) * 8;
        float sk = 0.f;
#pragma unroll
        for (int j = 0; j < 8; j++) { float b = ksT[d0 + j][tok]; sk = fmaf(b, b, sk); }
        sk += __shfl_xor_sync(0xffffffffu, sk, 1);
        sk += __shfl_xor_sync(0xffffffffu, sk, 2);
        float ik = 1.f / fmaxf(sqrtf(sk), 1e-12f);
#pragma unroll
        for (int j = 0; j < 8; j++) ksT[d0 + j][tok] *= ik;
    }
    __syncthreads();

    float scale = expf(fminf(logit_scale[h], 4.6051701859880914f));

    int ti = t >> 4, tj = t & 15;
    int i0 = ti * 4, j0 = tj * 4;
    float sv[4][4];
#pragma unroll
    for (int r = 0; r < 4; r++)
#pragma unroll
        for (int c = 0; c < 4; c++) sv[r][c] = 0.f;

#pragma unroll
    for (int kk = 0; kk < 32; kk++) {
        float4 kq = *(const float4*)&ksT[kk][j0];
        float qr[4];
#pragma unroll
        for (int r = 0; r < 4; r++) qr[r] = qs[i0 + r][kk];
#pragma unroll
        for (int r = 0; r < 4; r++) {
            sv[r][0] = fmaf(qr[r], kq.x, sv[r][0]);
            sv[r][1] = fmaf(qr[r], kq.y, sv[r][1]);
            sv[r][2] = fmaf(qr[r], kq.z, sv[r][2]);
            sv[r][3] = fmaf(qr[r], kq.w, sv[r][3]);
        }
    }

    int li[4], lj[4];
#pragma unroll
    for (int r = 0; r < 4; r++) li[r] = lab[i0 + r];
#pragma unroll
    for (int c = 0; c < 4; c++) lj[c] = lab[j0 + c];
    const float* btab = g_bias16 + (size_t)h * 4096;

#pragma unroll
    for (int r = 0; r < 4; r++) {
        float4 b4 = *(const float4*)(btab + (i0 + r) * 64 + j0);
        sv[r][0] = fmaf(sv[r][0], scale, b4.x) + ((lj[0] != li[r]) ? -100.f : 0.f);
        sv[r][1] = fmaf(sv[r][1], scale, b4.y) + ((lj[1] != li[r]) ? -100.f : 0.f);
        sv[r][2] = fmaf(sv[r][2], scale, b4.z) + ((lj[2] != li[r]) ? -100.f : 0.f);
        sv[r][3] = fmaf(sv[r][3], scale, b4.w) + ((lj[3] != li[r]) ? -100.f : 0.f);
        float m = fmaxf(fmaxf(sv[r][0], sv[r][1]), fmaxf(sv[r][2], sv[r][3]));
#pragma unroll
        for (int o = 1; o < 16; o <<= 1) m = fmaxf(m, __shfl_xor_sync(0xffffffffu, m, o));
        float s = 0.f;
#pragma unroll
        for (int c = 0; c < 4; c++) { sv[r][c] = expf(sv[r][c] - m); s += sv[r][c]; }
#pragma unroll
        for (int o = 1; o < 16; o <<= 1) s += __shfl_xor_sync(0xffffffffu, s, o);
        float inv = 1.f / s;
        float4 p = make_float4(sv[r][0] * inv, sv[r][1] * inv, sv[r][2] * inv, sv[r][3] * inv);
        *(float4*)&Ss[i0 + r][j0] = p;
    }
    __syncthreads();

    int tr = t >> 3, td = t & 7;
    int ip = tr * 2, d0 = td * 4;
    float po[2][4];
#pragma unroll
    for (int r = 0; r < 2; r++)
#pragma unroll
        for (int c = 0; c < 4; c++) po[r][c] = 0.f;

#pragma unroll
    for (int j4 = 0; j4 < 16; j4++) {
        float4 s4[2];
#pragma unroll
        for (int r = 0; r < 2; r++) s4[r] = *(const float4*)&Ss[ip + r][j4 * 4];
        float4 v4[4];
#pragma unroll
        for (int c = 0; c < 4; c++) v4[c] = *(const float4*)&vs[j4 * 4 + c][d0];
#pragma unroll
        for (int r = 0; r < 2; r++) {
            po[r][0] = fmaf(s4[r].x, v4[0].x, po[r][0]);
            po[r][1] = fmaf(s4[r].x, v4[0].y, po[r][1]);
            po[r][2] = fmaf(s4[r].x, v4[0].z, po[r][2]);
            po[r][3] = fmaf(s4[r].x, v4[0].w, po[r][3]);
            po[r][0] = fmaf(s4[r].y, v4[1].x, po[r][0]);
            po[r][1] = fmaf(s4[r].y, v4[1].y, po[r][1]);
            po[r][2] = fmaf(s4[r].y, v4[1].z, po[r][2]);
            po[r][3] = fmaf(s4[r].y, v4[1].w, po[r][3]);
            po[r][0] = fmaf(s4[r].z, v4[2].x, po[r][0]);
            po[r][1] = fmaf(s4[r].z, v4[2].y, po[r][1]);
            po[r][2] = fmaf(s4[r].z, v4[2].z, po[r][2]);
            po[r][3] = fmaf(s4[r].z, v4[2].w, po[r][3]);
            po[r][0] = fmaf(s4[r].w, v4[3].x, po[r][0]);
            po[r][1] = fmaf(s4[r].w, v4[3].y, po[r][1]);
            po[r][2] = fmaf(s4[r].w, v4[3].z, po[r][2]);
            po[r][3] = fmaf(s4[r].w, v4[3].w, po[r][3]);
        }
    }
#pragma unroll
    for (int r = 0; r < 2; r++) {
        float4 o4 = make_float4(tf32r(po[r][0]), tf32r(po[r][1]),
                                tf32r(po[r][2]), tf32r(po[r][3]));
        *(float4*)(g_attnout + ((size_t)win * 64 + ip + r) * 256 + h * 32 + d0) = o4;
    }
}

// ---------------- block reduction helper ----------------
__device__ __forceinline__ float block_sum_256(float v, float* sh) {
    int t = threadIdx.x;
#pragma unroll
    for (int o = 16; o > 0; o >>= 1) v += __shfl_xor_sync(0xffffffffu, v, o);
    if ((t & 31) == 0) sh[t >> 5] = v;
    __syncthreads();
    if (t < 32) {
        float r = (t < 8) ? sh[t] : 0.f;
#pragma unroll
        for (int o = 4; o > 0; o >>= 1) r += __shfl_xor_sync(0xffffffffu, r, o);
        if (t == 0) sh[0] = r;
    }
    __syncthreads();
    float r = sh[0];
    __syncthreads();
    return r;
}

__global__ __launch_bounds__(256) void ln_res1_kernel(const float* __restrict__ x,
                                                      const float* __restrict__ g,
                                                      const float* __restrict__ b) {
    __shared__ float sh[8];
    int row = blockIdx.x;
    int t = threadIdx.x;
    int bb = row >> 12;
    int l = row & 4095;
    int r = l >> 6, c = l & 63;
    int rs = (r + 64 - SHIFT_) & 63, cs = (c + 64 - SHIFT_) & 63;
    int win = bb * 64 + (rs >> 3) * 8 + (cs >> 3);
    int n = (rs & 7) * 8 + (cs & 7);
    float y = g_tmp[((size_t)win * 64 + n) * 256 + t];
    float m = block_sum_256(y, sh) * (1.f / 256.f);
    float d = y - m;
    float v = block_sum_256(d * d, sh) * (1.f / 256.f);
    float o = d * rsqrtf(v + 1e-5f) * g[t] + b[t];
    float xr = x[(size_t)row * 256 + t] + o;
    g_xr[(size_t)row * 256 + t] = xr;
    g_xrt[(size_t)row * 256 + t] = tf32r(xr);
}

__global__ __launch_bounds__(256) void ln_res2_kernel(float* __restrict__ out,
                                                      const float* __restrict__ g,
                                                      const float* __restrict__ b) {
    __shared__ float sh[8];
    int row = blockIdx.x;
    int t = threadIdx.x;
    float y = g_tmp[(size_t)row * 256 + t];
    float m = block_sum_256(y, sh) * (1.f / 256.f);
    float d = y - m;
    float v = block_sum_256(d * d, sh) * (1.f / 256.f);
    float o = d * rsqrtf(v + 1e-5f) * g[t] + b[t];
    out[(size_t)row * 256 + t] = g_xr[(size_t)row * 256 + t] + o;
}

// ---------------- launch ----------------
extern "C" void kernel_launch(void* const* d_in, const int* in_sizes, int n_in,
                              void* d_out, int out_size) {
    const float* x        = (const float*)d_in[0];
    const float* norm1_g  = (const float*)d_in[1];
    const float* norm1_b  = (const float*)d_in[2];
    const float* qkv_w    = (const float*)d_in[3];
    const float* q_bias   = (const float*)d_in[4];
    const float* v_bias   = (const float*)d_in[5];
    const float* logit_sc = (const float*)d_in[6];
    const float* cpb_w1   = (const float*)d_in[7];
    const float* cpb_b1   = (const float*)d_in[8];
    const float* cpb_w2   = (const float*)d_in[9];
    const float* proj_w   = (const float*)d_in[10];
    const float* proj_b   = (const float*)d_in[11];
    const float* norm2_g  = (const float*)d_in[12];
    const float* norm2_b  = (const float*)d_in[13];
    const float* fc1_w    = (const float*)d_in[14];
    const float* fc1_b    = (const float*)d_in[15];
    const float* fc2_w    = (const float*)d_in[16];
    const float* fc2_b    = (const float*)d_in[17];
    float* out = (float*)d_out;

    float *p_xw, *p_qkv, *p_attnout, *p_tmp, *p_xrt, *p_hdn, *p_qkvb, *p_wt;
    cudaGetSymbolAddress((void**)&p_xw, g_xw);
    cudaGetSymbolAddress((void**)&p_qkv, g_qkv);
    cudaGetSymbolAddress((void**)&p_attnout, g_attnout);
    cudaGetSymbolAddress((void**)&p_tmp, g_tmp);
    cudaGetSymbolAddress((void**)&p_xrt, g_xrt);
    cudaGetSymbolAddress((void**)&p_hdn, g_hdn);
    cudaGetSymbolAddress((void**)&p_qkvb, g_qkvb);
    cudaGetSymbolAddress((void**)&p_wt, g_wt);

    const int GSMEM = GSTAGES * SLOTB;   // 92160 bytes
    cudaFuncSetAttribute(mma_gemm_kernel,
                         cudaFuncAttributeMaxDynamicSharedMemorySize, GSMEM);

    fill_qkvb_kernel<<<1, 768>>>(q_bias, v_bias);
    cpb_kernel<<<1, 256>>>(cpb_w1, cpb_b1, cpb_w2);
    bias16_kernel<<<(HEADS * NTOK * NTOK) / 256, 256>>>();
    round_w_kernel<<<768, 256>>>(qkv_w, proj_w, fc1_w, fc2_w);
    gather_round_kernel<<<(M_ROWS * 64) / 256, 256>>>(x);

    // M blocks = 131072/256 = 512
    mma_gemm_kernel<<<dim3(6, 512), 256, GSMEM>>>(p_xw, p_wt + WT_QKV, p_qkvb, p_qkv, 768, 256, 0);

    attn_kernel<<<(M_ROWS / NTOK) * HEADS, 256>>>(logit_sc);

    mma_gemm_kernel<<<dim3(2, 512), 256, GSMEM>>>(p_attnout, p_wt + WT_PROJ, proj_b, p_tmp, 256, 256, 0);

    ln_res1_kernel<<<M_ROWS, 256>>>(x, norm1_g, norm1_b);

    mma_gemm_kernel<<<dim3(8, 512), 256, GSMEM>>>(p_xrt, p_wt + WT_FC1, fc1_b, p_hdn, 1024, 256, 1);
    mma_gemm_kernel<<<dim3(2, 512), 256, GSMEM>>>(p_hdn, p_wt + WT_FC2, fc2_b, p_tmp, 256, 1024, 0);

    ln_res2_kernel<<<M_ROWS, 256>>>(out, norm2_g, norm2_b);
}

// round 10
// speedup vs baseline: 1.3784x; 1.3784x over previous
#include <cuda_runtime.h>
#include <cuda_fp16.h>
#include <math.h>
#include <stdint.h>

#define DIMC 256
#define HEADS 8
#define NTOK 64
#define BATCH 32
#define LTOK 4096
#define M_ROWS (BATCH*LTOK)  // 131072
#define SHIFT_ 4

// ---------------- scratch ----------------
static __device__ __half g_xwh[(size_t)M_ROWS * DIMC];         // fp16 windowed x
static __device__ float  g_qkv[(size_t)M_ROWS * 3 * DIMC];     // fp32 (attn consumes)
static __device__ __half g_attnout[(size_t)M_ROWS * DIMC];     // fp16 (proj A)
static __device__ float  g_tmp[(size_t)M_ROWS * DIMC];         // fp32 (LN input)
static __device__ float  g_xr[(size_t)M_ROWS * DIMC];          // fp32 residual
static __device__ __half g_xrt[(size_t)M_ROWS * DIMC];         // fp16 (fc1 A)
static __device__ __half g_hdn[(size_t)M_ROWS * 4 * DIMC];     // fp16 (fc2 A)
static __device__ __half g_wth[786432];                        // fp16 weights
static __device__ float  g_cpb[225 * HEADS];
static __device__ float  g_bias16[HEADS * NTOK * NTOK];
static __device__ float  g_qkvb[3 * DIMC];

#define WT_QKV 0
#define WT_PROJ 196608
#define WT_FC1 262144
#define WT_FC2 524288

// ---------------- tiny setup kernels ----------------
__global__ void fill_qkvb_kernel(const float* __restrict__ q_bias,
                                 const float* __restrict__ v_bias) {
    int t = threadIdx.x;
    float v;
    if (t < 256)      v = q_bias[t];
    else if (t < 512) v = 0.f;
    else              v = v_bias[t - 512];
    g_qkvb[t] = v;
}

__global__ void cpb_kernel(const float* __restrict__ w1, const float* __restrict__ b1,
                           const float* __restrict__ w2) {
    int i = threadIdx.x;
    if (i >= 225) return;
    float a  = (float)(i / 15) - 7.f;
    float bb = (float)(i % 15) - 7.f;
    float f0 = a  * (8.f / 7.f);
    float f1 = bb * (8.f / 7.f);
    f0 = copysignf(log2f(fabsf(f0) + 1.f) * (1.f / 3.f), f0);
    f1 = copysignf(log2f(fabsf(f1) + 1.f) * (1.f / 3.f), f1);
    float acc[HEADS];
#pragma unroll
    for (int h = 0; h < HEADS; h++) acc[h] = 0.f;
    for (int u = 0; u < 512; u++) {
        float hu = fmaf(w1[2 * u], f0, fmaf(w1[2 * u + 1], f1, b1[u]));
        hu = fmaxf(hu, 0.f);
#pragma unroll
        for (int h = 0; h < HEADS; h++) acc[h] = fmaf(hu, w2[h * 512 + u], acc[h]);
    }
#pragma unroll
    for (int h = 0; h < HEADS; h++) g_cpb[i * HEADS + h] = acc[h];
}

__global__ void bias16_kernel() {
    int gid = blockIdx.x * blockDim.x + threadIdx.x;
    if (gid >= HEADS * NTOK * NTOK) return;
    int h = gid >> 12;
    int ij = gid & 4095;
    int i = ij >> 6, j = ij & 63;
    int dr = (i >> 3) - (j >> 3);
    int dc = (i & 7) - (j & 7);
    int idx = (dr + 7) * 15 + (dc + 7);
    float x = g_cpb[idx * HEADS + h];
    g_bias16[gid] = 16.f / (1.f + expf(-x));
}

__global__ void round_w_kernel(const float* __restrict__ qkv_w, const float* __restrict__ proj_w,
                               const float* __restrict__ fc1_w, const float* __restrict__ fc2_w) {
    int i4 = blockIdx.x * blockDim.x + threadIdx.x;
    if (i4 >= 196608) return;
    const float* src;
    int off = i4 * 4;
    if (off < WT_PROJ)           { src = qkv_w  + off; }
    else if (off < WT_FC1)       { src = proj_w + (off - WT_PROJ); }
    else if (off < WT_FC2)       { src = fc1_w  + (off - WT_FC1); }
    else                         { src = fc2_w  + (off - WT_FC2); }
    float4 v = *(const float4*)src;
    __half2* dst = (__half2*)(g_wth + off);
    dst[0] = __floats2half2_rn(v.x, v.y);
    dst[1] = __floats2half2_rn(v.z, v.w);
}

__global__ void gather_round_kernel(const float* __restrict__ x) {
    int t = blockIdx.x * blockDim.x + threadIdx.x;
    int m = t >> 6, c4 = t & 63;
    int win = m >> 6, n = m & 63;
    int b = win >> 6, wr = (win >> 3) & 7, wc = win & 7;
    int r = (wr * 8 + (n >> 3) + SHIFT_) & 63;
    int c = (wc * 8 + (n & 7) + SHIFT_) & 63;
    float4 v = ((const float4*)(x + ((size_t)b * LTOK + r * 64 + c) * DIMC))[c4];
    __half2* dst = (__half2*)(g_xwh + (size_t)m * DIMC + c4 * 4);
    dst[0] = __floats2half2_rn(v.x, v.y);
    dst[1] = __floats2half2_rn(v.z, v.w);
}

// ---------------- fp16 mma.sync GEMM: 128x128 CTA tile, 8 warps 64x32, BK=32 ----------------
// C[M,N] = A[M,K] @ W[N,K]^T + bias. A,W fp16; accumulate fp32.
#define ROWU 20                    // uint32 per smem row (16 data + 4 pad)
#define AROWB (ROWU * 4)           // 80 bytes
#define T_STAGEB (128 * AROWB)     // 10240 per operand tile
#define SLOTB (2 * T_STAGEB)       // 20480
#define GSTAGES 3

#define CP16(sm_, gp_) asm volatile("cp.async.cg.shared.global [%0], [%1], 16;" :: "r"(sm_), "l"(gp_))
#define CPCOMMIT() asm volatile("cp.async.commit_group;" ::: "memory")

__global__ __launch_bounds__(256, 2) void mma_gemm_kernel(
    const __half* __restrict__ A, const __half* __restrict__ W,
    const float* __restrict__ bias, void* __restrict__ Cout,
    int N, int K, int half_gelu_out) {
    extern __shared__ char dsm[];
    uint32_t* smu = (uint32_t*)dsm;
    int tid = threadIdx.x;
    int wid = tid >> 5, lane = tid & 31;
    int wm = wid >> 2, wn = wid & 3;       // warp tile (wm*64, wn*32)
    int brow = blockIdx.y * 128, bcol = blockIdx.x * 128;
    int lq = lane >> 2, lr = lane & 3;

    // cp.async: each row needs 4 x 16B chunks (64B of halves). 2 threads/row,
    // thread covers adjacent chunk pair {cc, cc+1}: smem bytes cc*16, cc*16+16;
    // global halves k0+cc*8, k0+cc*8+8.
    int crow = tid >> 1;                       // 0..127
    int cc = (tid & 1) * 2;                    // 0 or 2
    const __half* aptr = A + (size_t)(brow + crow) * K + cc * 8;
    const __half* wptr = W + (size_t)(bcol + crow) * K + cc * 8;
    uint32_t sbase = (uint32_t)__cvta_generic_to_shared(dsm);
    uint32_t aoff = sbase + crow * AROWB + cc * 16;
    uint32_t woff = aoff + T_STAGEB;

    float acc[4][4][4];
#pragma unroll
    for (int mi = 0; mi < 4; mi++)
#pragma unroll
        for (int ni = 0; ni < 4; ni++)
#pragma unroll
            for (int r = 0; r < 4; r++) acc[mi][ni][r] = 0.f;

    int KT = K >> 5;
#pragma unroll
    for (int p = 0; p < 2; p++) {
        uint32_t bo = p * (uint32_t)SLOTB;
        int k0 = p * 32;
        CP16(aoff + bo, aptr + k0); CP16(aoff + bo + 16, aptr + k0 + 8);
        CP16(woff + bo, wptr + k0); CP16(woff + bo + 16, wptr + k0 + 8);
        CPCOMMIT();
    }

    for (int kt = 0; kt < KT; kt++) {
        if (kt == KT - 1) asm volatile("cp.async.wait_group 0;" ::: "memory");
        else              asm volatile("cp.async.wait_group 1;" ::: "memory");
        __syncthreads();
        if (kt + 2 < KT) {
            uint32_t bo = ((kt + 2) % GSTAGES) * (uint32_t)SLOTB;
            int k0 = (kt + 2) * 32;
            CP16(aoff + bo, aptr + k0); CP16(aoff + bo + 16, aptr + k0 + 8);
            CP16(woff + bo, wptr + k0); CP16(woff + bo + 16, wptr + k0 + 8);
        }
        CPCOMMIT();

        const uint32_t* sa = smu + (kt % GSTAGES) * (SLOTB / 4);
        const uint32_t* sw = sa + (T_STAGEB / 4);
#pragma unroll
        for (int kp = 0; kp < 16; kp += 8) {   // two k16 steps
            uint32_t af[4][4];
#pragma unroll
            for (int mi = 0; mi < 4; mi++) {
                int rb = wm * 64 + mi * 16 + lq;
                af[mi][0] = sa[rb * ROWU + kp + lr];
                af[mi][1] = sa[(rb + 8) * ROWU + kp + lr];
                af[mi][2] = sa[rb * ROWU + kp + lr + 4];
                af[mi][3] = sa[(rb + 8) * ROWU + kp + lr + 4];
            }
            uint32_t bf[4][2];
#pragma unroll
            for (int ni = 0; ni < 4; ni++) {
                int nb = wn * 32 + ni * 8 + lq;
                bf[ni][0] = sw[nb * ROWU + kp + lr];
                bf[ni][1] = sw[nb * ROWU + kp + lr + 4];
            }
#pragma unroll
            for (int mi = 0; mi < 4; mi++)
#pragma unroll
                for (int ni = 0; ni < 4; ni++) {
                    asm volatile(
                        "mma.sync.aligned.m16n8k16.row.col.f32.f16.f16.f32 "
                        "{%0,%1,%2,%3}, {%4,%5,%6,%7}, {%8,%9}, {%0,%1,%2,%3};"
                        : "+f"(acc[mi][ni][0]), "+f"(acc[mi][ni][1]),
                          "+f"(acc[mi][ni][2]), "+f"(acc[mi][ni][3])
                        : "r"(af[mi][0]), "r"(af[mi][1]), "r"(af[mi][2]), "r"(af[mi][3]),
                          "r"(bf[ni][0]), "r"(bf[ni][1]));
                }
        }
    }

#pragma unroll
    for (int mi = 0; mi < 4; mi++) {
#pragma unroll
        for (int ni = 0; ni < 4; ni++) {
            int col = bcol + wn * 32 + ni * 8 + lr * 2;
            float b0 = bias[col], b1 = bias[col + 1];
            int rr = brow + wm * 64 + mi * 16 + lq;
            float v0 = acc[mi][ni][0] + b0;
            float v1 = acc[mi][ni][1] + b1;
            float v2 = acc[mi][ni][2] + b0;
            float v3 = acc[mi][ni][3] + b1;
            if (half_gelu_out) {
                v0 = 0.5f * v0 * (1.f + erff(v0 * 0.70710678118654752f));
                v1 = 0.5f * v1 * (1.f + erff(v1 * 0.70710678118654752f));
                v2 = 0.5f * v2 * (1.f + erff(v2 * 0.70710678118654752f));
                v3 = 0.5f * v3 * (1.f + erff(v3 * 0.70710678118654752f));
                __half* C = (__half*)Cout;
                *(__half2*)(C + (size_t)rr * N + col) = __floats2half2_rn(v0, v1);
                *(__half2*)(C + (size_t)(rr + 8) * N + col) = __floats2half2_rn(v2, v3);
            } else {
                float* C = (float*)Cout;
                *(float2*)(C + (size_t)rr * N + col) = make_float2(v0, v1);
                *(float2*)(C + (size_t)(rr + 8) * N + col) = make_float2(v2, v3);
            }
        }
    }
}

// ---------------- fused window attention (fp32 compute, fp16 output) ----------------
__global__ __launch_bounds__(256) void attn_kernel(const float* __restrict__ logit_scale) {
    __shared__ float qs[64][36];
    __shared__ float ksT[32][68];
    __shared__ float vs[64][36];
    __shared__ float Ss[64][68];
    __shared__ int lab[64];

    int blk = blockIdx.x;
    int win = blk >> 3, h = blk & 7;
    int t = threadIdx.x;

    size_t base = (size_t)win * 64 * 768;
#pragma unroll
    for (int f = t; f < 512; f += 256) {
        int n = f >> 3, d4 = (f & 7) * 4;
        const float* rowp = g_qkv + base + (size_t)n * 768 + h * 32 + d4;
        float4 q4 = *(const float4*)(rowp);
        float4 k4 = *(const float4*)(rowp + 256);
        float4 v4 = *(const float4*)(rowp + 512);
        *(float4*)&qs[n][d4] = q4;
        ksT[d4 + 0][n] = k4.x; ksT[d4 + 1][n] = k4.y;
        ksT[d4 + 2][n] = k4.z; ksT[d4 + 3][n] = k4.w;
        *(float4*)&vs[n][d4] = v4;
    }
    if (t < 64) {
        int wr = (win >> 3) & 7, wc = win & 7;
        int rs = wr * 8 + (t >> 3), cs = wc * 8 + (t & 7);
        int lr2 = rs < 56 ? 0 : (rs < 60 ? 1 : 2);
        int lc2 = cs < 56 ? 0 : (cs < 60 ? 1 : 2);
        lab[t] = lr2 * 3 + lc2;
    }
    __syncthreads();

    {
        int row = t >> 2, j0 = (t & 3) * 8;
        float sq = 0.f;
#pragma unroll
        for (int j = 0; j < 8; j++) { float a = qs[row][j0 + j]; sq = fmaf(a, a, sq); }
        sq += __shfl_xor_sync(0xffffffffu, sq, 1);
        sq += __shfl_xor_sync(0xffffffffu, sq, 2);
        float iq = 1.f / fmaxf(sqrtf(sq), 1e-12f);
#pragma unroll
        for (int j = 0; j < 8; j++) qs[row][j0 + j] *= iq;
    }
    {
        int tok = t >> 2, d0 = (t & 3) * 8;
        float sk = 0.f;
#pragma unroll
        for (int j = 0; j < 8; j++) { float b = ksT[d0 + j][tok]; sk = fmaf(b, b, sk); }
        sk += __shfl_xor_sync(0xffffffffu, sk, 1);
        sk += __shfl_xor_sync(0xffffffffu, sk, 2);
        float ik = 1.f / fmaxf(sqrtf(sk), 1e-12f);
#pragma unroll
        for (int j = 0; j < 8; j++) ksT[d0 + j][tok] *= ik;
    }
    __syncthreads();

    float scale = expf(fminf(logit_scale[h], 4.6051701859880914f));

    int ti = t >> 4, tj = t & 15;
    int i0 = ti * 4, j0 = tj * 4;
    float sv[4][4];
#pragma unroll
    for (int r = 0; r < 4; r++)
#pragma unroll
        for (int c = 0; c < 4; c++) sv[r][c] = 0.f;

#pragma unroll
    for (int kk = 0; kk < 32; kk++) {
        float4 kq = *(const float4*)&ksT[kk][j0];
        float qr[4];
#pragma unroll
        for (int r = 0; r < 4; r++) qr[r] = qs[i0 + r][kk];
#pragma unroll
        for (int r = 0; r < 4; r++) {
            sv[r][0] = fmaf(qr[r], kq.x, sv[r][0]);
            sv[r][1] = fmaf(qr[r], kq.y, sv[r][1]);
            sv[r][2] = fmaf(qr[r], kq.z, sv[r][2]);
            sv[r][3] = fmaf(qr[r], kq.w, sv[r][3]);
        }
    }

    int li[4], lj[4];
#pragma unroll
    for (int r = 0; r < 4; r++) li[r] = lab[i0 + r];
#pragma unroll
    for (int c = 0; c < 4; c++) lj[c] = lab[j0 + c];
    const float* btab = g_bias16 + (size_t)h * 4096;

#pragma unroll
    for (int r = 0; r < 4; r++) {
        float4 b4 = *(const float4*)(btab + (i0 + r) * 64 + j0);
        sv[r][0] = fmaf(sv[r][0], scale, b4.x) + ((lj[0] != li[r]) ? -100.f : 0.f);
        sv[r][1] = fmaf(sv[r][1], scale, b4.y) + ((lj[1] != li[r]) ? -100.f : 0.f);
        sv[r][2] = fmaf(sv[r][2], scale, b4.z) + ((lj[2] != li[r]) ? -100.f : 0.f);
        sv[r][3] = fmaf(sv[r][3], scale, b4.w) + ((lj[3] != li[r]) ? -100.f : 0.f);
        float m = fmaxf(fmaxf(sv[r][0], sv[r][1]), fmaxf(sv[r][2], sv[r][3]));
#pragma unroll
        for (int o = 1; o < 16; o <<= 1) m = fmaxf(m, __shfl_xor_sync(0xffffffffu, m, o));
        float s = 0.f;
#pragma unroll
        for (int c = 0; c < 4; c++) { sv[r][c] = expf(sv[r][c] - m); s += sv[r][c]; }
#pragma unroll
        for (int o = 1; o < 16; o <<= 1) s += __shfl_xor_sync(0xffffffffu, s, o);
        float inv = 1.f / s;
        float4 p = make_float4(sv[r][0] * inv, sv[r][1] * inv, sv[r][2] * inv, sv[r][3] * inv);
        *(float4*)&Ss[i0 + r][j0] = p;
    }
    __syncthreads();

    int tr = t >> 3, td = t & 7;
    int ip = tr * 2, d0 = td * 4;
    float po[2][4];
#pragma unroll
    for (int r = 0; r < 2; r++)
#pragma unroll
        for (int c = 0; c < 4; c++) po[r][c] = 0.f;

#pragma unroll
    for (int j4 = 0; j4 < 16; j4++) {
        float4 s4[2];
#pragma unroll
        for (int r = 0; r < 2; r++) s4[r] = *(const float4*)&Ss[ip + r][j4 * 4];
        float4 v4[4];
#pragma unroll
        for (int c = 0; c < 4; c++) v4[c] = *(const float4*)&vs[j4 * 4 + c][d0];
#pragma unroll
        for (int r = 0; r < 2; r++) {
            po[r][0] = fmaf(s4[r].x, v4[0].x, po[r][0]);
            po[r][1] = fmaf(s4[r].x, v4[0].y, po[r][1]);
            po[r][2] = fmaf(s4[r].x, v4[0].z, po[r][2]);
            po[r][3] = fmaf(s4[r].x, v4[0].w, po[r][3]);
            po[r][0] = fmaf(s4[r].y, v4[1].x, po[r][0]);
            po[r][1] = fmaf(s4[r].y, v4[1].y, po[r][1]);
            po[r][2] = fmaf(s4[r].y, v4[1].z, po[r][2]);
            po[r][3] = fmaf(s4[r].y, v4[1].w, po[r][3]);
            po[r][0] = fmaf(s4[r].z, v4[2].x, po[r][0]);
            po[r][1] = fmaf(s4[r].z, v4[2].y, po[r][1]);
            po[r][2] = fmaf(s4[r].z, v4[2].z, po[r][2]);
            po[r][3] = fmaf(s4[r].z, v4[2].w, po[r][3]);
            po[r][0] = fmaf(s4[r].w, v4[3].x, po[r][0]);
            po[r][1] = fmaf(s4[r].w, v4[3].y, po[r][1]);
            po[r][2] = fmaf(s4[r].w, v4[3].z, po[r][2]);
            po[r][3] = fmaf(s4[r].w, v4[3].w, po[r][3]);
        }
    }
#pragma unroll
    for (int r = 0; r < 2; r++) {
        __half2* dst = (__half2*)(g_attnout + ((size_t)win * 64 + ip + r) * 256 + h * 32 + d0);
        dst[0] = __floats2half2_rn(po[r][0], po[r][1]);
        dst[1] = __floats2half2_rn(po[r][2], po[r][3]);
    }
}

// ---------------- block reduction helper ----------------
__device__ __forceinline__ float block_sum_256(float v, float* sh) {
    int t = threadIdx.x;
#pragma unroll
    for (int o = 16; o > 0; o >>= 1) v += __shfl_xor_sync(0xffffffffu, v, o);
    if ((t & 31) == 0) sh[t >> 5] = v;
    __syncthreads();
    if (t < 32) {
        float r = (t < 8) ? sh[t] : 0.f;
#pragma unroll
        for (int o = 4; o > 0; o >>= 1) r += __shfl_xor_sync(0xffffffffu, r, o);
        if (t == 0) sh[0] = r;
    }
    __syncthreads();
    float r = sh[0];
    __syncthreads();
    return r;
}

__global__ __launch_bounds__(256) void ln_res1_kernel(const float* __restrict__ x,
                                                      const float* __restrict__ g,
                                                      const float* __restrict__ b) {
    __shared__ float sh[8];
    int row = blockIdx.x;
    int t = threadIdx.x;
    int bb = row >> 12;
    int l = row & 4095;
    int r = l >> 6, c = l & 63;
    int rs = (r + 64 - SHIFT_) & 63, cs = (c + 64 - SHIFT_) & 63;
    int win = bb * 64 + (rs >> 3) * 8 + (cs >> 3);
    int n = (rs & 7) * 8 + (cs & 7);
    float y = g_tmp[((size_t)win * 64 + n) * 256 + t];
    float m = block_sum_256(y, sh) * (1.f / 256.f);
    float d = y - m;
    float v = block_sum_256(d * d, sh) * (1.f / 256.f);
    float o = d * rsqrtf(v + 1e-5f) * g[t] + b[t];
    float xr = x[(size_t)row * 256 + t] + o;
    g_xr[(size_t)row * 256 + t] = xr;
    g_xrt[(size_t)row * 256 + t] = __float2half(xr);
}

__global__ __launch_bounds__(256) void ln_res2_kernel(float* __restrict__ out,
                                                      const float* __restrict__ g,
                                                      const float* __restrict__ b) {
    __shared__ float sh[8];
    int row = blockIdx.x;
    int t = threadIdx.x;
    float y = g_tmp[(size_t)row * 256 + t];
    float m = block_sum_256(y, sh) * (1.f / 256.f);
    float d = y - m;
    float v = block_sum_256(d * d, sh) * (1.f / 256.f);
    float o = d * rsqrtf(v + 1e-5f) * g[t] + b[t];
    out[(size_t)row * 256 + t] = g_xr[(size_t)row * 256 + t] + o;
}

// ---------------- launch ----------------
extern "C" void kernel_launch(void* const* d_in, const int* in_sizes, int n_in,
                              void* d_out, int out_size) {
    const float* x        = (const float*)d_in[0];
    const float* norm1_g  = (const float*)d_in[1];
    const float* norm1_b  = (const float*)d_in[2];
    const float* qkv_w    = (const float*)d_in[3];
    const float* q_bias   = (const float*)d_in[4];
    const float* v_bias   = (const float*)d_in[5];
    const float* logit_sc = (const float*)d_in[6];
    const float* cpb_w1   = (const float*)d_in[7];
    const float* cpb_b1   = (const float*)d_in[8];
    const float* cpb_w2   = (const float*)d_in[9];
    const float* proj_w   = (const float*)d_in[10];
    const float* proj_b   = (const float*)d_in[11];
    const float* norm2_g  = (const float*)d_in[12];
    const float* norm2_b  = (const float*)d_in[13];
    const float* fc1_w    = (const float*)d_in[14];
    const float* fc1_b    = (const float*)d_in[15];
    const float* fc2_w    = (const float*)d_in[16];
    const float* fc2_b    = (const float*)d_in[17];
    float* out = (float*)d_out;

    float *p_qkv, *p_tmp, *p_qkvb;
    __half *p_xwh, *p_attnout, *p_xrt, *p_hdn, *p_wth;
    cudaGetSymbolAddress((void**)&p_xwh, g_xwh);
    cudaGetSymbolAddress((void**)&p_qkv, g_qkv);
    cudaGetSymbolAddress((void**)&p_attnout, g_attnout);
    cudaGetSymbolAddress((void**)&p_tmp, g_tmp);
    cudaGetSymbolAddress((void**)&p_xrt, g_xrt);
    cudaGetSymbolAddress((void**)&p_hdn, g_hdn);
    cudaGetSymbolAddress((void**)&p_qkvb, g_qkvb);
    cudaGetSymbolAddress((void**)&p_wth, g_wth);

    const int GSMEM = GSTAGES * SLOTB;   // 61440 bytes
    cudaFuncSetAttribute(mma_gemm_kernel,
                         cudaFuncAttributeMaxDynamicSharedMemorySize, GSMEM);

    fill_qkvb_kernel<<<1, 768>>>(q_bias, v_bias);
    cpb_kernel<<<1, 256>>>(cpb_w1, cpb_b1, cpb_w2);
    bias16_kernel<<<(HEADS * NTOK * NTOK) / 256, 256>>>();
    round_w_kernel<<<768, 256>>>(qkv_w, proj_w, fc1_w, fc2_w);
    gather_round_kernel<<<(M_ROWS * 64) / 256, 256>>>(x);

    // QKV: out fp32 (attn consumes full precision)
    mma_gemm_kernel<<<dim3(6, 1024), 256, GSMEM>>>(p_xwh, p_wth + WT_QKV, p_qkvb, p_qkv, 768, 256, 0);

    attn_kernel<<<(M_ROWS / NTOK) * HEADS, 256>>>(logit_sc);

    mma_gemm_kernel<<<dim3(2, 1024), 256, GSMEM>>>(p_attnout, p_wth + WT_PROJ, proj_b, p_tmp, 256, 256, 0);

    ln_res1_kernel<<<M_ROWS, 256>>>(x, norm1_g, norm1_b);

    // fc1: half+gelu out
    mma_gemm_kernel<<<dim3(8, 1024), 256, GSMEM>>>(p_xrt, p_wth + WT_FC1, fc1_b, p_hdn, 1024, 256, 1);
    mma_gemm_kernel<<<dim3(2, 1024), 256, GSMEM>>>(p_hdn, p_wth + WT_FC2, fc2_b, p_tmp, 256, 1024, 0);

    ln_res2_kernel<<<M_ROWS, 256>>>(out, norm2_g, norm2_b);
}

// round 11
// speedup vs baseline: 1.4262x; 1.0347x over previous
#include <cuda_runtime.h>
#include <cuda_fp16.h>
#include <math.h>
#include <stdint.h>

#define DIMC 256
#define HEADS 8
#define NTOK 64
#define BATCH 32
#define LTOK 4096
#define M_ROWS (BATCH*LTOK)  // 131072
#define SHIFT_ 4

// ---------------- scratch ----------------
static __device__ __half g_xwh[(size_t)M_ROWS * DIMC];         // fp16 windowed x
static __device__ float  g_qkv[(size_t)M_ROWS * 3 * DIMC];     // fp32 (attn consumes)
static __device__ __half g_attnout[(size_t)M_ROWS * DIMC];     // fp16 (proj A)
static __device__ float  g_tmp[(size_t)M_ROWS * DIMC];         // fp32 (LN input)
static __device__ float  g_xr[(size_t)M_ROWS * DIMC];          // fp32 residual
static __device__ __half g_xrt[(size_t)M_ROWS * DIMC];         // fp16 (fc1 A)
static __device__ __half g_hdn[(size_t)M_ROWS * 4 * DIMC];     // fp16 (fc2 A)
static __device__ __half g_wth[786432];                        // fp16 weights
static __device__ float  g_cpb[225 * HEADS];
static __device__ float  g_bias16[HEADS * NTOK * NTOK];
static __device__ float  g_qkvb[3 * DIMC];

#define WT_QKV 0
#define WT_PROJ 196608
#define WT_FC1 262144
#define WT_FC2 524288

// ---------------- tiny setup kernels ----------------
__global__ void fill_qkvb_kernel(const float* __restrict__ q_bias,
                                 const float* __restrict__ v_bias) {
    int t = threadIdx.x;
    float v;
    if (t < 256)      v = q_bias[t];
    else if (t < 512) v = 0.f;
    else              v = v_bias[t - 512];
    g_qkvb[t] = v;
}

__global__ void cpb_kernel(const float* __restrict__ w1, const float* __restrict__ b1,
                           const float* __restrict__ w2) {
    int i = threadIdx.x;
    if (i >= 225) return;
    float a  = (float)(i / 15) - 7.f;
    float bb = (float)(i % 15) - 7.f;
    float f0 = a  * (8.f / 7.f);
    float f1 = bb * (8.f / 7.f);
    f0 = copysignf(log2f(fabsf(f0) + 1.f) * (1.f / 3.f), f0);
    f1 = copysignf(log2f(fabsf(f1) + 1.f) * (1.f / 3.f), f1);
    float acc[HEADS];
#pragma unroll
    for (int h = 0; h < HEADS; h++) acc[h] = 0.f;
    for (int u = 0; u < 512; u++) {
        float hu = fmaf(w1[2 * u], f0, fmaf(w1[2 * u + 1], f1, b1[u]));
        hu = fmaxf(hu, 0.f);
#pragma unroll
        for (int h = 0; h < HEADS; h++) acc[h] = fmaf(hu, w2[h * 512 + u], acc[h]);
    }
#pragma unroll
    for (int h = 0; h < HEADS; h++) g_cpb[i * HEADS + h] = acc[h];
}

__global__ void bias16_kernel() {
    int gid = blockIdx.x * blockDim.x + threadIdx.x;
    if (gid >= HEADS * NTOK * NTOK) return;
    int h = gid >> 12;
    int ij = gid & 4095;
    int i = ij >> 6, j = ij & 63;
    int dr = (i >> 3) - (j >> 3);
    int dc = (i & 7) - (j & 7);
    int idx = (dr + 7) * 15 + (dc + 7);
    float x = g_cpb[idx * HEADS + h];
    g_bias16[gid] = 16.f / (1.f + expf(-x));
}

__global__ void round_w_kernel(const float* __restrict__ qkv_w, const float* __restrict__ proj_w,
                               const float* __restrict__ fc1_w, const float* __restrict__ fc2_w) {
    int i4 = blockIdx.x * blockDim.x + threadIdx.x;
    if (i4 >= 196608) return;
    const float* src;
    int off = i4 * 4;
    if (off < WT_PROJ)           { src = qkv_w  + off; }
    else if (off < WT_FC1)       { src = proj_w + (off - WT_PROJ); }
    else if (off < WT_FC2)       { src = fc1_w  + (off - WT_FC1); }
    else                         { src = fc2_w  + (off - WT_FC2); }
    float4 v = *(const float4*)src;
    __half2* dst = (__half2*)(g_wth + off);
    dst[0] = __floats2half2_rn(v.x, v.y);
    dst[1] = __floats2half2_rn(v.z, v.w);
}

__global__ void gather_round_kernel(const float* __restrict__ x) {
    int t = blockIdx.x * blockDim.x + threadIdx.x;
    int m = t >> 6, c4 = t & 63;
    int win = m >> 6, n = m & 63;
    int b = win >> 6, wr = (win >> 3) & 7, wc = win & 7;
    int r = (wr * 8 + (n >> 3) + SHIFT_) & 63;
    int c = (wc * 8 + (n & 7) + SHIFT_) & 63;
    float4 v = ((const float4*)(x + ((size_t)b * LTOK + r * 64 + c) * DIMC))[c4];
    __half2* dst = (__half2*)(g_xwh + (size_t)m * DIMC + c4 * 4);
    dst[0] = __floats2half2_rn(v.x, v.y);
    dst[1] = __floats2half2_rn(v.z, v.w);
}

// ---------------- fp16 mma.sync GEMM: 128x128 CTA tile, 8 warps 64x32, BK=32 ----------------
// C[M,N] = A[M,K] @ W[N,K]^T + bias. A,W fp16; accumulate fp32. ldmatrix fragment loads.
#define ROWU 20                    // uint32 per smem row (16 data + 4 pad)
#define AROWB (ROWU * 4)           // 80 bytes
#define T_STAGEB (128 * AROWB)     // 10240 per operand tile
#define SLOTB (2 * T_STAGEB)       // 20480
#define GSTAGES 3

#define CP16(sm_, gp_) asm volatile("cp.async.cg.shared.global [%0], [%1], 16;" :: "r"(sm_), "l"(gp_))
#define CPCOMMIT() asm volatile("cp.async.commit_group;" ::: "memory")
#define LDSM4(r0_, r1_, r2_, r3_, addr_) \
    asm volatile("ldmatrix.sync.aligned.m8n8.x4.shared.b16 {%0,%1,%2,%3}, [%4];" \
                 : "=r"(r0_), "=r"(r1_), "=r"(r2_), "=r"(r3_) : "r"(addr_))

__global__ __launch_bounds__(256, 2) void mma_gemm_kernel(
    const __half* __restrict__ A, const __half* __restrict__ W,
    const float* __restrict__ bias, void* __restrict__ Cout,
    int N, int K, int half_gelu_out) {
    extern __shared__ char dsm[];
    int tid = threadIdx.x;
    int wid = tid >> 5, lane = tid & 31;
    int wm = wid >> 2, wn = wid & 3;       // warp tile (wm*64, wn*32)
    int brow = blockIdx.y * 128, bcol = blockIdx.x * 128;
    int lq = lane >> 2, lr = lane & 3;

    // cp.async: 2 threads/row, thread covers chunk pair {cc, cc+1}
    int crow = tid >> 1;
    int cc = (tid & 1) * 2;
    const __half* aptr = A + (size_t)(brow + crow) * K + cc * 8;
    const __half* wptr = W + (size_t)(bcol + crow) * K + cc * 8;
    uint32_t sbase = (uint32_t)__cvta_generic_to_shared(dsm);
    uint32_t aoff = sbase + crow * AROWB + cc * 16;
    uint32_t woff = aoff + T_STAGEB;

    // ldmatrix per-lane base offsets
    // A: lanes 0-7 -> rows +0 (k-lo), 8-15 -> rows +8 (k-lo), 16-23 -> rows +0 (k-hi), 24-31 -> rows +8 (k-hi)
    uint32_t a_lrow = (uint32_t)(wm * 64 + (lane & 7) + ((lane >> 3) & 1) * 8);
    uint32_t a_lbyte = (uint32_t)((lane >> 4) * 16);
    uint32_t a_lbase = sbase + a_lrow * AROWB + a_lbyte;
    // B: lanes 0-7 -> rows +0 k-lo, 8-15 -> rows +0 k-hi, 16-23 -> rows +8 k-lo, 24-31 -> rows +8 k-hi
    uint32_t b_lrow = (uint32_t)(wn * 32 + ((lane >> 4) & 1) * 8 + (lane & 7));
    uint32_t b_lbyte = (uint32_t)(((lane >> 3) & 1) * 16);
    uint32_t b_lbase = sbase + T_STAGEB + b_lrow * AROWB + b_lbyte;

    float acc[4][4][4];
#pragma unroll
    for (int mi = 0; mi < 4; mi++)
#pragma unroll
        for (int ni = 0; ni < 4; ni++)
#pragma unroll
            for (int r = 0; r < 4; r++) acc[mi][ni][r] = 0.f;

    int KT = K >> 5;
#pragma unroll
    for (int p = 0; p < 2; p++) {
        uint32_t bo = p * (uint32_t)SLOTB;
        int k0 = p * 32;
        CP16(aoff + bo, aptr + k0); CP16(aoff + bo + 16, aptr + k0 + 8);
        CP16(woff + bo, wptr + k0); CP16(woff + bo + 16, wptr + k0 + 8);
        CPCOMMIT();
    }

    for (int kt = 0; kt < KT; kt++) {
        if (kt == KT - 1) asm volatile("cp.async.wait_group 0;" ::: "memory");
        else              asm volatile("cp.async.wait_group 1;" ::: "memory");
        __syncthreads();
        if (kt + 2 < KT) {
            uint32_t bo = ((kt + 2) % GSTAGES) * (uint32_t)SLOTB;
            int k0 = (kt + 2) * 32;
            CP16(aoff + bo, aptr + k0); CP16(aoff + bo + 16, aptr + k0 + 8);
            CP16(woff + bo, wptr + k0); CP16(woff + bo + 16, wptr + k0 + 8);
        }
        CPCOMMIT();

        uint32_t so = ((uint32_t)(kt % GSTAGES)) * SLOTB;
#pragma unroll
        for (int kp = 0; kp < 16; kp += 8) {   // two k16 steps; kp*4 = byte offset
            uint32_t af[4][4];
#pragma unroll
            for (int mi = 0; mi < 4; mi++) {
                LDSM4(af[mi][0], af[mi][1], af[mi][2], af[mi][3],
                      a_lbase + so + (uint32_t)(mi * 16) * AROWB + kp * 4);
            }
            uint32_t bf[4][2];
#pragma unroll
            for (int p = 0; p < 2; p++) {
                LDSM4(bf[p * 2][0], bf[p * 2][1], bf[p * 2 + 1][0], bf[p * 2 + 1][1],
                      b_lbase + so + (uint32_t)(p * 16) * AROWB + kp * 4);
            }
#pragma unroll
            for (int mi = 0; mi < 4; mi++)
#pragma unroll
                for (int ni = 0; ni < 4; ni++) {
                    asm volatile(
                        "mma.sync.aligned.m16n8k16.row.col.f32.f16.f16.f32 "
                        "{%0,%1,%2,%3}, {%4,%5,%6,%7}, {%8,%9}, {%0,%1,%2,%3};"
                        : "+f"(acc[mi][ni][0]), "+f"(acc[mi][ni][1]),
                          "+f"(acc[mi][ni][2]), "+f"(acc[mi][ni][3])
                        : "r"(af[mi][0]), "r"(af[mi][1]), "r"(af[mi][2]), "r"(af[mi][3]),
                          "r"(bf[ni][0]), "r"(bf[ni][1]));
                }
        }
    }

#pragma unroll
    for (int mi = 0; mi < 4; mi++) {
#pragma unroll
        for (int ni = 0; ni < 4; ni++) {
            int col = bcol + wn * 32 + ni * 8 + lr * 2;
            float b0 = bias[col], b1 = bias[col + 1];
            int rr = brow + wm * 64 + mi * 16 + lq;
            float v0 = acc[mi][ni][0] + b0;
            float v1 = acc[mi][ni][1] + b1;
            float v2 = acc[mi][ni][2] + b0;
            float v3 = acc[mi][ni][3] + b1;
            if (half_gelu_out) {
                v0 = 0.5f * v0 * (1.f + erff(v0 * 0.70710678118654752f));
                v1 = 0.5f * v1 * (1.f + erff(v1 * 0.70710678118654752f));
                v2 = 0.5f * v2 * (1.f + erff(v2 * 0.70710678118654752f));
                v3 = 0.5f * v3 * (1.f + erff(v3 * 0.70710678118654752f));
                __half* C = (__half*)Cout;
                *(__half2*)(C + (size_t)rr * N + col) = __floats2half2_rn(v0, v1);
                *(__half2*)(C + (size_t)(rr + 8) * N + col) = __floats2half2_rn(v2, v3);
            } else {
                float* C = (float*)Cout;
                *(float2*)(C + (size_t)rr * N + col) = make_float2(v0, v1);
                *(float2*)(C + (size_t)(rr + 8) * N + col) = make_float2(v2, v3);
            }
        }
    }
}

// ---------------- fused window attention (fp32 compute, fp16 output) ----------------
__global__ __launch_bounds__(256) void attn_kernel(const float* __restrict__ logit_scale) {
    __shared__ float qs[64][36];
    __shared__ float ksT[32][68];
    __shared__ float vs[64][36];
    __shared__ float Ss[64][68];
    __shared__ int lab[64];

    int blk = blockIdx.x;
    int win = blk >> 3, h = blk & 7;
    int t = threadIdx.x;

    size_t base = (size_t)win * 64 * 768;
#pragma unroll
    for (int f = t; f < 512; f += 256) {
        int n = f >> 3, d4 = (f & 7) * 4;
        const float* rowp = g_qkv + base + (size_t)n * 768 + h * 32 + d4;
        float4 q4 = *(const float4*)(rowp);
        float4 k4 = *(const float4*)(rowp + 256);
        float4 v4 = *(const float4*)(rowp + 512);
        *(float4*)&qs[n][d4] = q4;
        ksT[d4 + 0][n] = k4.x; ksT[d4 + 1][n] = k4.y;
        ksT[d4 + 2][n] = k4.z; ksT[d4 + 3][n] = k4.w;
        *(float4*)&vs[n][d4] = v4;
    }
    if (t < 64) {
        int wr = (win >> 3) & 7, wc = win & 7;
        int rs = wr * 8 + (t >> 3), cs = wc * 8 + (t & 7);
        int lr2 = rs < 56 ? 0 : (rs < 60 ? 1 : 2);
        int lc2 = cs < 56 ? 0 : (cs < 60 ? 1 : 2);
        lab[t] = lr2 * 3 + lc2;
    }
    __syncthreads();

    {
        int row = t >> 2, j0 = (t & 3) * 8;
        float sq = 0.f;
#pragma unroll
        for (int j = 0; j < 8; j++) { float a = qs[row][j0 + j]; sq = fmaf(a, a, sq); }
        sq += __shfl_xor_sync(0xffffffffu, sq, 1);
        sq += __shfl_xor_sync(0xffffffffu, sq, 2);
        float iq = 1.f / fmaxf(sqrtf(sq), 1e-12f);
#pragma unroll
        for (int j = 0; j < 8; j++) qs[row][j0 + j] *= iq;
    }
    {
        int tok = t >> 2, d0 = (t & 3) * 8;
        float sk = 0.f;
#pragma unroll
        for (int j = 0; j < 8; j++) { float b = ksT[d0 + j][tok]; sk = fmaf(b, b, sk); }
        sk += __shfl_xor_sync(0xffffffffu, sk, 1);
        sk += __shfl_xor_sync(0xffffffffu, sk, 2);
        float ik = 1.f / fmaxf(sqrtf(sk), 1e-12f);
#pragma unroll
        for (int j = 0; j < 8; j++) ksT[d0 + j][tok] *= ik;
    }
    __syncthreads();

    float scale = expf(fminf(logit_scale[h], 4.6051701859880914f));

    int ti = t >> 4, tj = t & 15;
    int i0 = ti * 4, j0 = tj * 4;
    float sv[4][4];
#pragma unroll
    for (int r = 0; r < 4; r++)
#pragma unroll
        for (int c = 0; c < 4; c++) sv[r][c] = 0.f;

#pragma unroll
    for (int kk = 0; kk < 32; kk++) {
        float4 kq = *(const float4*)&ksT[kk][j0];
        float qr[4];
#pragma unroll
        for (int r = 0; r < 4; r++) qr[r] = qs[i0 + r][kk];
#pragma unroll
        for (int r = 0; r < 4; r++) {
            sv[r][0] = fmaf(qr[r], kq.x, sv[r][0]);
            sv[r][1] = fmaf(qr[r], kq.y, sv[r][1]);
            sv[r][2] = fmaf(qr[r], kq.z, sv[r][2]);
            sv[r][3] = fmaf(qr[r], kq.w, sv[r][3]);
        }
    }

    int li[4], lj[4];
#pragma unroll
    for (int r = 0; r < 4; r++) li[r] = lab[i0 + r];
#pragma unroll
    for (int c = 0; c < 4; c++) lj[c] = lab[j0 + c];
    const float* btab = g_bias16 + (size_t)h * 4096;

#pragma unroll
    for (int r = 0; r < 4; r++) {
        float4 b4 = *(const float4*)(btab + (i0 + r) * 64 + j0);
        sv[r][0] = fmaf(sv[r][0], scale, b4.x) + ((lj[0] != li[r]) ? -100.f : 0.f);
        sv[r][1] = fmaf(sv[r][1], scale, b4.y) + ((lj[1] != li[r]) ? -100.f : 0.f);
        sv[r][2] = fmaf(sv[r][2], scale, b4.z) + ((lj[2] != li[r]) ? -100.f : 0.f);
        sv[r][3] = fmaf(sv[r][3], scale, b4.w) + ((lj[3] != li[r]) ? -100.f : 0.f);
        float m = fmaxf(fmaxf(sv[r][0], sv[r][1]), fmaxf(sv[r][2], sv[r][3]));
#pragma unroll
        for (int o = 1; o < 16; o <<= 1) m = fmaxf(m, __shfl_xor_sync(0xffffffffu, m, o));
        float s = 0.f;
#pragma unroll
        for (int c = 0; c < 4; c++) { sv[r][c] = expf(sv[r][c] - m); s += sv[r][c]; }
#pragma unroll
        for (int o = 1; o < 16; o <<= 1) s += __shfl_xor_sync(0xffffffffu, s, o);
        float inv = 1.f / s;
        float4 p = make_float4(sv[r][0] * inv, sv[r][1] * inv, sv[r][2] * inv, sv[r][3] * inv);
        *(float4*)&Ss[i0 + r][j0] = p;
    }
    __syncthreads();

    int tr = t >> 3, td = t & 7;
    int ip = tr * 2, d0 = td * 4;
    float po[2][4];
#pragma unroll
    for (int r = 0; r < 2; r++)
#pragma unroll
        for (int c = 0; c < 4; c++) po[r][c] = 0.f;

#pragma unroll
    for (int j4 = 0; j4 < 16; j4++) {
        float4 s4[2];
#pragma unroll
        for (int r = 0; r < 2; r++) s4[r] = *(const float4*)&Ss[ip + r][j4 * 4];
        float4 v4[4];
#pragma unroll
        for (int c = 0; c < 4; c++) v4[c] = *(const float4*)&vs[j4 * 4 + c][d0];
#pragma unroll
        for (int r = 0; r < 2; r++) {
            po[r][0] = fmaf(s4[r].x, v4[0].x, po[r][0]);
            po[r][1] = fmaf(s4[r].x, v4[0].y, po[r][1]);
            po[r][2] = fmaf(s4[r].x, v4[0].z, po[r][2]);
            po[r][3] = fmaf(s4[r].x, v4[0].w, po[r][3]);
            po[r][0] = fmaf(s4[r].y, v4[1].x, po[r][0]);
            po[r][1] = fmaf(s4[r].y, v4[1].y, po[r][1]);
            po[r][2] = fmaf(s4[r].y, v4[1].z, po[r][2]);
            po[r][3] = fmaf(s4[r].y, v4[1].w, po[r][3]);
            po[r][0] = fmaf(s4[r].z, v4[2].x, po[r][0]);
            po[r][1] = fmaf(s4[r].z, v4[2].y, po[r][1]);
            po[r][2] = fmaf(s4[r].z, v4[2].z, po[r][2]);
            po[r][3] = fmaf(s4[r].z, v4[2].w, po[r][3]);
            po[r][0] = fmaf(s4[r].w, v4[3].x, po[r][0]);
            po[r][1] = fmaf(s4[r].w, v4[3].y, po[r][1]);
            po[r][2] = fmaf(s4[r].w, v4[3].z, po[r][2]);
            po[r][3] = fmaf(s4[r].w, v4[3].w, po[r][3]);
        }
    }
#pragma unroll
    for (int r = 0; r < 2; r++) {
        __half2* dst = (__half2*)(g_attnout + ((size_t)win * 64 + ip + r) * 256 + h * 32 + d0);
        dst[0] = __floats2half2_rn(po[r][0], po[r][1]);
        dst[1] = __floats2half2_rn(po[r][2], po[r][3]);
    }
}

// ---------------- block reduction helper ----------------
__device__ __forceinline__ float block_sum_256(float v, float* sh) {
    int t = threadIdx.x;
#pragma unroll
    for (int o = 16; o > 0; o >>= 1) v += __shfl_xor_sync(0xffffffffu, v, o);
    if ((t & 31) == 0) sh[t >> 5] = v;
    __syncthreads();
    if (t < 32) {
        float r = (t < 8) ? sh[t] : 0.f;
#pragma unroll
        for (int o = 4; o > 0; o >>= 1) r += __shfl_xor_sync(0xffffffffu, r, o);
        if (t == 0) sh[0] = r;
    }
    __syncthreads();
    float r = sh[0];
    __syncthreads();
    return r;
}

__global__ __launch_bounds__(256) void ln_res1_kernel(const float* __restrict__ x,
                                                      const float* __restrict__ g,
                                                      const float* __restrict__ b) {
    __shared__ float sh[8];
    int row = blockIdx.x;
    int t = threadIdx.x;
    int bb = row >> 12;
    int l = row & 4095;
    int r = l >> 6, c = l & 63;
    int rs = (r + 64 - SHIFT_) & 63, cs = (c + 64 - SHIFT_) & 63;
    int win = bb * 64 + (rs >> 3) * 8 + (cs >> 3);
    int n = (rs & 7) * 8 + (cs & 7);
    float y = g_tmp[((size_t)win * 64 + n) * 256 + t];
    float m = block_sum_256(y, sh) * (1.f / 256.f);
    float d = y - m;
    float v = block_sum_256(d * d, sh) * (1.f / 256.f);
    float o = d * rsqrtf(v + 1e-5f) * g[t] + b[t];
    float xr = x[(size_t)row * 256 + t] + o;
    g_xr[(size_t)row * 256 + t] = xr;
    g_xrt[(size_t)row * 256 + t] = __float2half(xr);
}

__global__ __launch_bounds__(256) void ln_res2_kernel(float* __restrict__ out,
                                                      const float* __restrict__ g,
                                                      const float* __restrict__ b) {
    __shared__ float sh[8];
    int row = blockIdx.x;
    int t = threadIdx.x;
    float y = g_tmp[(size_t)row * 256 + t];
    float m = block_sum_256(y, sh) * (1.f / 256.f);
    float d = y - m;
    float v = block_sum_256(d * d, sh) * (1.f / 256.f);
    float o = d * rsqrtf(v + 1e-5f) * g[t] + b[t];
    out[(size_t)row * 256 + t] = g_xr[(size_t)row * 256 + t] + o;
}

// ---------------- launch ----------------
extern "C" void kernel_launch(void* const* d_in, const int* in_sizes, int n_in,
                              void* d_out, int out_size) {
    const float* x        = (const float*)d_in[0];
    const float* norm1_g  = (const float*)d_in[1];
    const float* norm1_b  = (const float*)d_in[2];
    const float* qkv_w    = (const float*)d_in[3];
    const float* q_bias   = (const float*)d_in[4];
    const float* v_bias   = (const float*)d_in[5];
    const float* logit_sc = (const float*)d_in[6];
    const float* cpb_w1   = (const float*)d_in[7];
    const float* cpb_b1   = (const float*)d_in[8];
    const float* cpb_w2   = (const float*)d_in[9];
    const float* proj_w   = (const float*)d_in[10];
    const float* proj_b   = (const float*)d_in[11];
    const float* norm2_g  = (const float*)d_in[12];
    const float* norm2_b  = (const float*)d_in[13];
    const float* fc1_w    = (const float*)d_in[14];
    const float* fc1_b    = (const float*)d_in[15];
    const float* fc2_w    = (const float*)d_in[16];
    const float* fc2_b    = (const float*)d_in[17];
    float* out = (float*)d_out;

    float *p_qkv, *p_tmp, *p_qkvb;
    __half *p_xwh, *p_attnout, *p_xrt, *p_hdn, *p_wth;
    cudaGetSymbolAddress((void**)&p_xwh, g_xwh);
    cudaGetSymbolAddress((void**)&p_qkv, g_qkv);
    cudaGetSymbolAddress((void**)&p_attnout, g_attnout);
    cudaGetSymbolAddress((void**)&p_tmp, g_tmp);
    cudaGetSymbolAddress((void**)&p_xrt, g_xrt);
    cudaGetSymbolAddress((void**)&p_hdn, g_hdn);
    cudaGetSymbolAddress((void**)&p_qkvb, g_qkvb);
    cudaGetSymbolAddress((void**)&p_wth, g_wth);

    const int GSMEM = GSTAGES * SLOTB;   // 61440 bytes
    cudaFuncSetAttribute(mma_gemm_kernel,
                         cudaFuncAttributeMaxDynamicSharedMemorySize, GSMEM);

    fill_qkvb_kernel<<<1, 768>>>(q_bias, v_bias);
    cpb_kernel<<<1, 256>>>(cpb_w1, cpb_b1, cpb_w2);
    bias16_kernel<<<(HEADS * NTOK * NTOK) / 256, 256>>>();
    round_w_kernel<<<768, 256>>>(qkv_w, proj_w, fc1_w, fc2_w);
    gather_round_kernel<<<(M_ROWS * 64) / 256, 256>>>(x);

    // QKV: out fp32 (attn consumes full precision)
    mma_gemm_kernel<<<dim3(6, 1024), 256, GSMEM>>>(p_xwh, p_wth + WT_QKV, p_qkvb, p_qkv, 768, 256, 0);

    attn_kernel<<<(M_ROWS / NTOK) * HEADS, 256>>>(logit_sc);

    mma_gemm_kernel<<<dim3(2, 1024), 256, GSMEM>>>(p_attnout, p_wth + WT_PROJ, proj_b, p_tmp, 256, 256, 0);

    ln_res1_kernel<<<M_ROWS, 256>>>(x, norm1_g, norm1_b);

    // fc1: half+gelu out
    mma_gemm_kernel<<<dim3(8, 1024), 256, GSMEM>>>(p_xrt, p_wth + WT_FC1, fc1_b, p_hdn, 1024, 256, 1);
    mma_gemm_kernel<<<dim3(2, 1024), 256, GSMEM>>>(p_hdn, p_wth + WT_FC2, fc2_b, p_tmp, 256, 1024, 0);

    ln_res2_kernel<<<M_ROWS, 256>>>(out, norm2_g, norm2_b);
}